// round 11
// baseline (speedup 1.0000x reference)
#include <cuda_runtime.h>
#include <math.h>

// Problem constants
#define ES    8
#define DS    1024
#define HS    2048
#define DOUTS 1024
#define TS    8192
#define CAP   8192

// ---------------- scratch (device globals; allocations banned) ----------
__device__ int   g_cnt[ES];
__device__ int   g_tok[ES * CAP];
__device__ float g_wt [ES * CAP];
__device__ int   g_slot0[TS];
__device__ int   g_slot1[TS];
__device__ float g_Hb[(size_t)ES * CAP * HS];    // h = silu(g)*u*w  (512 MB)
__device__ float g_O[(size_t)ES * CAP * DOUTS];  // down proj output (256 MB)

// ---------------- routing ----------------------------------------------------
__global__ void zero_cnt_kernel() {
    if (threadIdx.x < ES) g_cnt[threadIdx.x] = 0;
}

__global__ void build_kernel(const int* __restrict__ idx,
                             const float* __restrict__ w) {
    int t = blockIdx.x * blockDim.x + threadIdx.x;
    if (t >= TS) return;
    int e0 = idx[2 * t];
    int e1 = idx[2 * t + 1];
    float w0 = w[2 * t];
    float w1 = w[2 * t + 1];
    if ((unsigned)e0 >= ES) e0 = 0;
    if ((unsigned)e1 >= ES) e1 = 0;
    if (e0 == e1) {
        int s = atomicAdd(&g_cnt[e0], 1);
        g_tok[e0 * CAP + s] = t;
        g_wt [e0 * CAP + s] = w0 + w1;
        g_slot0[t] = e0 * CAP + s;
        g_slot1[t] = -1;
    } else {
        int s0 = atomicAdd(&g_cnt[e0], 1);
        g_tok[e0 * CAP + s0] = t;
        g_wt [e0 * CAP + s0] = w0;
        int s1 = atomicAdd(&g_cnt[e1], 1);
        g_tok[e1 * CAP + s1] = t;
        g_wt [e1 * CAP + s1] = w1;
        g_slot0[t] = e0 * CAP + s0;
        g_slot1[t] = e1 * CAP + s1;
    }
}

// ---------------- fused gate+up GEMM (double-buffered, prefetch) -------------
// Tile: 128 gathered rows x 64 H-cols; dual accumulators (gate & up).
__global__ __launch_bounds__(256, 2)
void gateup_kernel(const float* __restrict__ X,
                   const float* __restrict__ Wg,
                   const float* __restrict__ Wu) {
    int e = blockIdx.z;
    int cnt = g_cnt[e];
    int m0 = blockIdx.x * 128;
    if (m0 >= cnt) return;
    int n0 = blockIdx.y * 64;

    __shared__ float As[2][8][128];
    __shared__ float Bg[2][8][64];
    __shared__ float Bu[2][8][64];

    int tid = threadIdx.x;

    // A loader: 128 rows x 8 k, one float4 per thread
    int rowA  = tid >> 1;
    int ksegA = (tid & 1) * 4;
    int slotA = m0 + rowA;
    int token = (slotA < cnt) ? g_tok[e * CAP + slotA] : 0;
    const float* Arow = X + (size_t)token * DS;

    // B loaders: threads 0..127 -> Wg panel, 128..255 -> Wu panel
    int rowB  = (tid & 127) >> 1;    // 0..63
    int ksegB = (tid & 1) * 4;
    bool doU = (tid >= 128);
    const float* Brow = (doU ? Wu : Wg) + ((size_t)e * HS + n0 + rowB) * DS;

    int tx = tid & 15;   // n micro (4 cols)
    int ty = tid >> 4;   // m micro (8 rows)

    float accG[8][4], accU[8][4];
#pragma unroll
    for (int i = 0; i < 8; i++)
#pragma unroll
        for (int j = 0; j < 4; j++) { accG[i][j] = 0.f; accU[i][j] = 0.f; }

    // prime: prefetch tile 0, store to buf 0
    float4 av = *(const float4*)(Arow + ksegA);
    float4 bv = *(const float4*)(Brow + ksegB);
    As[0][ksegA + 0][rowA] = av.x;
    As[0][ksegA + 1][rowA] = av.y;
    As[0][ksegA + 2][rowA] = av.z;
    As[0][ksegA + 3][rowA] = av.w;
    if (doU) {
        Bu[0][ksegB + 0][rowB] = bv.x;
        Bu[0][ksegB + 1][rowB] = bv.y;
        Bu[0][ksegB + 2][rowB] = bv.z;
        Bu[0][ksegB + 3][rowB] = bv.w;
    } else {
        Bg[0][ksegB + 0][rowB] = bv.x;
        Bg[0][ksegB + 1][rowB] = bv.y;
        Bg[0][ksegB + 2][rowB] = bv.z;
        Bg[0][ksegB + 3][rowB] = bv.w;
    }
    __syncthreads();

    for (int k0 = 0; k0 < DS; k0 += 8) {
        int buf = (k0 >> 3) & 1;
        // prefetch next tile into registers (overlaps with compute)
        if (k0 + 8 < DS) {
            av = *(const float4*)(Arow + k0 + 8 + ksegA);
            bv = *(const float4*)(Brow + k0 + 8 + ksegB);
        }
#pragma unroll
        for (int kk = 0; kk < 8; kk++) {
            float4 a0 = *(const float4*)&As[buf][kk][ty * 8];
            float4 a1 = *(const float4*)&As[buf][kk][ty * 8 + 4];
            float4 bgv = *(const float4*)&Bg[buf][kk][tx * 4];
            float4 buv = *(const float4*)&Bu[buf][kk][tx * 4];
            float am0 = a0.x, am1 = a0.y, am2 = a0.z, am3 = a0.w;
            float am4 = a1.x, am5 = a1.y, am6 = a1.z, am7 = a1.w;
#pragma unroll
            for (int j = 0; j < 4; j++) {
                float bgn = (j == 0) ? bgv.x : (j == 1) ? bgv.y : (j == 2) ? bgv.z : bgv.w;
                float bun = (j == 0) ? buv.x : (j == 1) ? buv.y : (j == 2) ? buv.z : buv.w;
                accG[0][j] = fmaf(am0, bgn, accG[0][j]);
                accG[1][j] = fmaf(am1, bgn, accG[1][j]);
                accG[2][j] = fmaf(am2, bgn, accG[2][j]);
                accG[3][j] = fmaf(am3, bgn, accG[3][j]);
                accG[4][j] = fmaf(am4, bgn, accG[4][j]);
                accG[5][j] = fmaf(am5, bgn, accG[5][j]);
                accG[6][j] = fmaf(am6, bgn, accG[6][j]);
                accG[7][j] = fmaf(am7, bgn, accG[7][j]);
                accU[0][j] = fmaf(am0, bun, accU[0][j]);
                accU[1][j] = fmaf(am1, bun, accU[1][j]);
                accU[2][j] = fmaf(am2, bun, accU[2][j]);
                accU[3][j] = fmaf(am3, bun, accU[3][j]);
                accU[4][j] = fmaf(am4, bun, accU[4][j]);
                accU[5][j] = fmaf(am5, bun, accU[5][j]);
                accU[6][j] = fmaf(am6, bun, accU[6][j]);
                accU[7][j] = fmaf(am7, bun, accU[7][j]);
            }
        }
        // store prefetched tile into the other buffer, then one sync
        if (k0 + 8 < DS) {
            int nb = buf ^ 1;
            As[nb][ksegA + 0][rowA] = av.x;
            As[nb][ksegA + 1][rowA] = av.y;
            As[nb][ksegA + 2][rowA] = av.z;
            As[nb][ksegA + 3][rowA] = av.w;
            if (doU) {
                Bu[nb][ksegB + 0][rowB] = bv.x;
                Bu[nb][ksegB + 1][rowB] = bv.y;
                Bu[nb][ksegB + 2][rowB] = bv.z;
                Bu[nb][ksegB + 3][rowB] = bv.w;
            } else {
                Bg[nb][ksegB + 0][rowB] = bv.x;
                Bg[nb][ksegB + 1][rowB] = bv.y;
                Bg[nb][ksegB + 2][rowB] = bv.z;
                Bg[nb][ksegB + 3][rowB] = bv.w;
            }
            __syncthreads();
        }
    }

    int ecap = e * CAP;
#pragma unroll
    for (int mi = 0; mi < 8; mi++) {
        int slot = m0 + ty * 8 + mi;
        if (slot >= cnt) continue;
        float wv = g_wt[ecap + slot];
        float* hr = g_Hb + (size_t)(ecap + slot) * HS + n0 + tx * 4;
        float g0 = accG[mi][0], g1 = accG[mi][1], g2 = accG[mi][2], g3 = accG[mi][3];
        float4 hv;
        hv.x = (g0 / (1.0f + __expf(-g0))) * accU[mi][0] * wv;
        hv.y = (g1 / (1.0f + __expf(-g1))) * accU[mi][1] * wv;
        hv.z = (g2 / (1.0f + __expf(-g2))) * accU[mi][2] * wv;
        hv.w = (g3 / (1.0f + __expf(-g3))) * accU[mi][3] * wv;
        *(float4*)hr = hv;
    }
}

// ---------------- down GEMM: O = H @ Wd^T (double-buffered, prefetch) --------
__global__ __launch_bounds__(256, 2)
void down_kernel(const float* __restrict__ Wd) {
    int e = blockIdx.z;
    int cnt = g_cnt[e];
    int m0 = blockIdx.x * 128;
    if (m0 >= cnt) return;
    int n0 = blockIdx.y * 128;

    const float* W = Wd + (size_t)e * DOUTS * HS;

    __shared__ float As[2][8][128];
    __shared__ float Bs[2][8][128];

    int tid  = threadIdx.x;
    int rowA = tid >> 1;
    int kseg = (tid & 1) * 4;

    const float* Arow = g_Hb + (size_t)(e * CAP + m0 + rowA) * HS;
    const float* Brow = W + (size_t)(n0 + rowA) * HS;

    int tx = tid & 15;
    int ty = tid >> 4;

    float acc[8][8];
#pragma unroll
    for (int i = 0; i < 8; i++)
#pragma unroll
        for (int j = 0; j < 8; j++) acc[i][j] = 0.f;

    float4 av = *(const float4*)(Arow + kseg);
    float4 bv = *(const float4*)(Brow + kseg);
    As[0][kseg + 0][rowA] = av.x;
    As[0][kseg + 1][rowA] = av.y;
    As[0][kseg + 2][rowA] = av.z;
    As[0][kseg + 3][rowA] = av.w;
    Bs[0][kseg + 0][rowA] = bv.x;
    Bs[0][kseg + 1][rowA] = bv.y;
    Bs[0][kseg + 2][rowA] = bv.z;
    Bs[0][kseg + 3][rowA] = bv.w;
    __syncthreads();

    for (int k0 = 0; k0 < HS; k0 += 8) {
        int buf = (k0 >> 3) & 1;
        if (k0 + 8 < HS) {
            av = *(const float4*)(Arow + k0 + 8 + kseg);
            bv = *(const float4*)(Brow + k0 + 8 + kseg);
        }
#pragma unroll
        for (int kk = 0; kk < 8; kk++) {
            float4 a0 = *(const float4*)&As[buf][kk][ty * 8];
            float4 a1 = *(const float4*)&As[buf][kk][ty * 8 + 4];
            float4 b0 = *(const float4*)&Bs[buf][kk][tx * 8];
            float4 b1 = *(const float4*)&Bs[buf][kk][tx * 8 + 4];
            float am0 = a0.x, am1 = a0.y, am2 = a0.z, am3 = a0.w;
            float am4 = a1.x, am5 = a1.y, am6 = a1.z, am7 = a1.w;
#pragma unroll
            for (int j = 0; j < 8; j++) {
                float bn = (j == 0) ? b0.x : (j == 1) ? b0.y : (j == 2) ? b0.z : (j == 3) ? b0.w
                          : (j == 4) ? b1.x : (j == 5) ? b1.y : (j == 6) ? b1.z : b1.w;
                acc[0][j] = fmaf(am0, bn, acc[0][j]);
                acc[1][j] = fmaf(am1, bn, acc[1][j]);
                acc[2][j] = fmaf(am2, bn, acc[2][j]);
                acc[3][j] = fmaf(am3, bn, acc[3][j]);
                acc[4][j] = fmaf(am4, bn, acc[4][j]);
                acc[5][j] = fmaf(am5, bn, acc[5][j]);
                acc[6][j] = fmaf(am6, bn, acc[6][j]);
                acc[7][j] = fmaf(am7, bn, acc[7][j]);
            }
        }
        if (k0 + 8 < HS) {
            int nb = buf ^ 1;
            As[nb][kseg + 0][rowA] = av.x;
            As[nb][kseg + 1][rowA] = av.y;
            As[nb][kseg + 2][rowA] = av.z;
            As[nb][kseg + 3][rowA] = av.w;
            Bs[nb][kseg + 0][rowA] = bv.x;
            Bs[nb][kseg + 1][rowA] = bv.y;
            Bs[nb][kseg + 2][rowA] = bv.z;
            Bs[nb][kseg + 3][rowA] = bv.w;
            __syncthreads();
        }
    }

    int ecap = e * CAP;
#pragma unroll
    for (int mi = 0; mi < 8; mi++) {
        int slot = m0 + ty * 8 + mi;
        if (slot >= cnt) continue;
        float* orow = g_O + (size_t)(ecap + slot) * DOUTS + n0 + tx * 8;
        float4 v0, v1;
        v0.x = acc[mi][0]; v0.y = acc[mi][1]; v0.z = acc[mi][2]; v0.w = acc[mi][3];
        v1.x = acc[mi][4]; v1.y = acc[mi][5]; v1.z = acc[mi][6]; v1.w = acc[mi][7];
        *(float4*)orow       = v0;
        *(float4*)(orow + 4) = v1;
    }
}

// ---------------- final combine ---------------------------------------------
__global__ void combine_kernel(float* __restrict__ out) {
    int i = blockIdx.x * blockDim.x + threadIdx.x;  // over TS*DOUTS/4
    if (i >= TS * (DOUTS / 4)) return;
    int t  = i / (DOUTS / 4);
    int d4 = i % (DOUTS / 4);
    const float4* O4 = (const float4*)g_O;
    float4 a = O4[(size_t)g_slot0[t] * (DOUTS / 4) + d4];
    int s1 = g_slot1[t];
    if (s1 >= 0) {
        float4 b = O4[(size_t)s1 * (DOUTS / 4) + d4];
        a.x += b.x; a.y += b.y; a.z += b.z; a.w += b.w;
    }
    ((float4*)out)[i] = a;
}

// ---------------- launch -----------------------------------------------------
extern "C" void kernel_launch(void* const* d_in, const int* in_sizes, int n_in,
                              void* d_out, int out_size) {
    const float* X   = (const float*)d_in[0];   // [T, D]
    const int*   idx = (const int*)d_in[1];     // [T, K] int32 (JAX default)
    const float* wts = (const float*)d_in[2];   // [T, K]
    const float* Wg  = (const float*)d_in[3];   // [E, H, D]
    const float* Wu  = (const float*)d_in[4];   // [E, H, D]
    const float* Wd  = (const float*)d_in[5];   // [E, DOUT, H]
    float* out = (float*)d_out;                 // [T, DOUT]

    zero_cnt_kernel<<<1, 32>>>();
    build_kernel<<<(TS + 255) / 256, 256>>>(idx, wts);

    dim3 gUp(CAP / 128, HS / 64, ES);           // 64 x 32 x 8 (early-exit on count)
    gateup_kernel<<<gUp, 256>>>(X, Wg, Wu);

    dim3 gDn(CAP / 128, DOUTS / 128, ES);       // 64 x 8 x 8
    down_kernel<<<gDn, 256>>>(Wd);

    combine_kernel<<<(TS * (DOUTS / 4) + 255) / 256, 256>>>(out);
}

// round 12
// speedup vs baseline: 1.0009x; 1.0009x over previous
#include <cuda_runtime.h>
#include <math.h>

// Problem constants
#define ES    8
#define DS    1024
#define HS    2048
#define DOUTS 1024
#define TS    8192
#define CAP   8192

// ---------------- scratch (device globals; allocations banned) ----------
__device__ int   g_cnt[ES];
__device__ int   g_tok[ES * CAP];
__device__ float g_wt [ES * CAP];
__device__ int   g_slot0[TS];
__device__ int   g_slot1[TS];
__device__ float g_Hb[(size_t)ES * CAP * HS];    // h = silu(g)*u*w  (512 MB)
__device__ float g_O[(size_t)ES * CAP * DOUTS];  // down proj output (256 MB)

// ---------------- routing ----------------------------------------------------
__global__ void zero_cnt_kernel() {
    if (threadIdx.x < ES) g_cnt[threadIdx.x] = 0;
}

__global__ void build_kernel(const int* __restrict__ idx,
                             const float* __restrict__ w) {
    int t = blockIdx.x * blockDim.x + threadIdx.x;
    if (t >= TS) return;
    int e0 = idx[2 * t];
    int e1 = idx[2 * t + 1];
    float w0 = w[2 * t];
    float w1 = w[2 * t + 1];
    if ((unsigned)e0 >= ES) e0 = 0;
    if ((unsigned)e1 >= ES) e1 = 0;
    if (e0 == e1) {
        int s = atomicAdd(&g_cnt[e0], 1);
        g_tok[e0 * CAP + s] = t;
        g_wt [e0 * CAP + s] = w0 + w1;
        g_slot0[t] = e0 * CAP + s;
        g_slot1[t] = -1;
    } else {
        int s0 = atomicAdd(&g_cnt[e0], 1);
        g_tok[e0 * CAP + s0] = t;
        g_wt [e0 * CAP + s0] = w0;
        int s1 = atomicAdd(&g_cnt[e1], 1);
        g_tok[e1 * CAP + s1] = t;
        g_wt [e1 * CAP + s1] = w1;
        g_slot0[t] = e0 * CAP + s0;
        g_slot1[t] = e1 * CAP + s1;
    }
}

// ---------------- fused gate+up GEMM (double-buffered, prefetch) -------------
// Tile: 128 gathered rows x 64 H-cols; dual accumulators (gate & up).
__global__ __launch_bounds__(256, 2)
void gateup_kernel(const float* __restrict__ X,
                   const float* __restrict__ Wg,
                   const float* __restrict__ Wu) {
    int e = blockIdx.z;
    int cnt = g_cnt[e];
    int m0 = blockIdx.x * 128;
    if (m0 >= cnt) return;
    int n0 = blockIdx.y * 64;

    __shared__ float As[2][8][128];
    __shared__ float Bg[2][8][64];
    __shared__ float Bu[2][8][64];

    int tid = threadIdx.x;

    // A loader: 128 rows x 8 k, one float4 per thread
    int rowA  = tid >> 1;
    int ksegA = (tid & 1) * 4;
    int slotA = m0 + rowA;
    int token = (slotA < cnt) ? g_tok[e * CAP + slotA] : 0;
    const float* Arow = X + (size_t)token * DS;

    // B loaders: threads 0..127 -> Wg panel, 128..255 -> Wu panel
    int rowB  = (tid & 127) >> 1;    // 0..63
    int ksegB = (tid & 1) * 4;
    bool doU = (tid >= 128);
    const float* Brow = (doU ? Wu : Wg) + ((size_t)e * HS + n0 + rowB) * DS;

    int tx = tid & 15;   // n micro (4 cols)
    int ty = tid >> 4;   // m micro (8 rows)

    float accG[8][4], accU[8][4];
#pragma unroll
    for (int i = 0; i < 8; i++)
#pragma unroll
        for (int j = 0; j < 4; j++) { accG[i][j] = 0.f; accU[i][j] = 0.f; }

    // prime: prefetch tile 0, store to buf 0
    float4 av = *(const float4*)(Arow + ksegA);
    float4 bv = *(const float4*)(Brow + ksegB);
    As[0][ksegA + 0][rowA] = av.x;
    As[0][ksegA + 1][rowA] = av.y;
    As[0][ksegA + 2][rowA] = av.z;
    As[0][ksegA + 3][rowA] = av.w;
    if (doU) {
        Bu[0][ksegB + 0][rowB] = bv.x;
        Bu[0][ksegB + 1][rowB] = bv.y;
        Bu[0][ksegB + 2][rowB] = bv.z;
        Bu[0][ksegB + 3][rowB] = bv.w;
    } else {
        Bg[0][ksegB + 0][rowB] = bv.x;
        Bg[0][ksegB + 1][rowB] = bv.y;
        Bg[0][ksegB + 2][rowB] = bv.z;
        Bg[0][ksegB + 3][rowB] = bv.w;
    }
    __syncthreads();

    for (int k0 = 0; k0 < DS; k0 += 8) {
        int buf = (k0 >> 3) & 1;
        // prefetch next tile into registers (overlaps with compute)
        if (k0 + 8 < DS) {
            av = *(const float4*)(Arow + k0 + 8 + ksegA);
            bv = *(const float4*)(Brow + k0 + 8 + ksegB);
        }
#pragma unroll
        for (int kk = 0; kk < 8; kk++) {
            float4 a0 = *(const float4*)&As[buf][kk][ty * 8];
            float4 a1 = *(const float4*)&As[buf][kk][ty * 8 + 4];
            float4 bgv = *(const float4*)&Bg[buf][kk][tx * 4];
            float4 buv = *(const float4*)&Bu[buf][kk][tx * 4];
            float am0 = a0.x, am1 = a0.y, am2 = a0.z, am3 = a0.w;
            float am4 = a1.x, am5 = a1.y, am6 = a1.z, am7 = a1.w;
#pragma unroll
            for (int j = 0; j < 4; j++) {
                float bgn = (j == 0) ? bgv.x : (j == 1) ? bgv.y : (j == 2) ? bgv.z : bgv.w;
                float bun = (j == 0) ? buv.x : (j == 1) ? buv.y : (j == 2) ? buv.z : buv.w;
                accG[0][j] = fmaf(am0, bgn, accG[0][j]);
                accG[1][j] = fmaf(am1, bgn, accG[1][j]);
                accG[2][j] = fmaf(am2, bgn, accG[2][j]);
                accG[3][j] = fmaf(am3, bgn, accG[3][j]);
                accG[4][j] = fmaf(am4, bgn, accG[4][j]);
                accG[5][j] = fmaf(am5, bgn, accG[5][j]);
                accG[6][j] = fmaf(am6, bgn, accG[6][j]);
                accG[7][j] = fmaf(am7, bgn, accG[7][j]);
                accU[0][j] = fmaf(am0, bun, accU[0][j]);
                accU[1][j] = fmaf(am1, bun, accU[1][j]);
                accU[2][j] = fmaf(am2, bun, accU[2][j]);
                accU[3][j] = fmaf(am3, bun, accU[3][j]);
                accU[4][j] = fmaf(am4, bun, accU[4][j]);
                accU[5][j] = fmaf(am5, bun, accU[5][j]);
                accU[6][j] = fmaf(am6, bun, accU[6][j]);
                accU[7][j] = fmaf(am7, bun, accU[7][j]);
            }
        }
        // store prefetched tile into the other buffer, then one sync
        if (k0 + 8 < DS) {
            int nb = buf ^ 1;
            As[nb][ksegA + 0][rowA] = av.x;
            As[nb][ksegA + 1][rowA] = av.y;
            As[nb][ksegA + 2][rowA] = av.z;
            As[nb][ksegA + 3][rowA] = av.w;
            if (doU) {
                Bu[nb][ksegB + 0][rowB] = bv.x;
                Bu[nb][ksegB + 1][rowB] = bv.y;
                Bu[nb][ksegB + 2][rowB] = bv.z;
                Bu[nb][ksegB + 3][rowB] = bv.w;
            } else {
                Bg[nb][ksegB + 0][rowB] = bv.x;
                Bg[nb][ksegB + 1][rowB] = bv.y;
                Bg[nb][ksegB + 2][rowB] = bv.z;
                Bg[nb][ksegB + 3][rowB] = bv.w;
            }
            __syncthreads();
        }
    }

    int ecap = e * CAP;
#pragma unroll
    for (int mi = 0; mi < 8; mi++) {
        int slot = m0 + ty * 8 + mi;
        if (slot >= cnt) continue;
        float wv = g_wt[ecap + slot];
        float* hr = g_Hb + (size_t)(ecap + slot) * HS + n0 + tx * 4;
        float g0 = accG[mi][0], g1 = accG[mi][1], g2 = accG[mi][2], g3 = accG[mi][3];
        float4 hv;
        hv.x = (g0 / (1.0f + __expf(-g0))) * accU[mi][0] * wv;
        hv.y = (g1 / (1.0f + __expf(-g1))) * accU[mi][1] * wv;
        hv.z = (g2 / (1.0f + __expf(-g2))) * accU[mi][2] * wv;
        hv.w = (g3 / (1.0f + __expf(-g3))) * accU[mi][3] * wv;
        *(float4*)hr = hv;
    }
}

// ---------------- down GEMM: O = H @ Wd^T (double-buffered, prefetch) --------
__global__ __launch_bounds__(256, 2)
void down_kernel(const float* __restrict__ Wd) {
    int e = blockIdx.z;
    int cnt = g_cnt[e];
    int m0 = blockIdx.x * 128;
    if (m0 >= cnt) return;
    int n0 = blockIdx.y * 128;

    const float* W = Wd + (size_t)e * DOUTS * HS;

    __shared__ float As[2][8][128];
    __shared__ float Bs[2][8][128];

    int tid  = threadIdx.x;
    int rowA = tid >> 1;
    int kseg = (tid & 1) * 4;

    const float* Arow = g_Hb + (size_t)(e * CAP + m0 + rowA) * HS;
    const float* Brow = W + (size_t)(n0 + rowA) * HS;

    int tx = tid & 15;
    int ty = tid >> 4;

    float acc[8][8];
#pragma unroll
    for (int i = 0; i < 8; i++)
#pragma unroll
        for (int j = 0; j < 8; j++) acc[i][j] = 0.f;

    float4 av = *(const float4*)(Arow + kseg);
    float4 bv = *(const float4*)(Brow + kseg);
    As[0][kseg + 0][rowA] = av.x;
    As[0][kseg + 1][rowA] = av.y;
    As[0][kseg + 2][rowA] = av.z;
    As[0][kseg + 3][rowA] = av.w;
    Bs[0][kseg + 0][rowA] = bv.x;
    Bs[0][kseg + 1][rowA] = bv.y;
    Bs[0][kseg + 2][rowA] = bv.z;
    Bs[0][kseg + 3][rowA] = bv.w;
    __syncthreads();

    for (int k0 = 0; k0 < HS; k0 += 8) {
        int buf = (k0 >> 3) & 1;
        if (k0 + 8 < HS) {
            av = *(const float4*)(Arow + k0 + 8 + kseg);
            bv = *(const float4*)(Brow + k0 + 8 + kseg);
        }
#pragma unroll
        for (int kk = 0; kk < 8; kk++) {
            float4 a0 = *(const float4*)&As[buf][kk][ty * 8];
            float4 a1 = *(const float4*)&As[buf][kk][ty * 8 + 4];
            float4 b0 = *(const float4*)&Bs[buf][kk][tx * 8];
            float4 b1 = *(const float4*)&Bs[buf][kk][tx * 8 + 4];
            float am0 = a0.x, am1 = a0.y, am2 = a0.z, am3 = a0.w;
            float am4 = a1.x, am5 = a1.y, am6 = a1.z, am7 = a1.w;
#pragma unroll
            for (int j = 0; j < 8; j++) {
                float bn = (j == 0) ? b0.x : (j == 1) ? b0.y : (j == 2) ? b0.z : (j == 3) ? b0.w
                          : (j == 4) ? b1.x : (j == 5) ? b1.y : (j == 6) ? b1.z : b1.w;
                acc[0][j] = fmaf(am0, bn, acc[0][j]);
                acc[1][j] = fmaf(am1, bn, acc[1][j]);
                acc[2][j] = fmaf(am2, bn, acc[2][j]);
                acc[3][j] = fmaf(am3, bn, acc[3][j]);
                acc[4][j] = fmaf(am4, bn, acc[4][j]);
                acc[5][j] = fmaf(am5, bn, acc[5][j]);
                acc[6][j] = fmaf(am6, bn, acc[6][j]);
                acc[7][j] = fmaf(am7, bn, acc[7][j]);
            }
        }
        if (k0 + 8 < HS) {
            int nb = buf ^ 1;
            As[nb][kseg + 0][rowA] = av.x;
            As[nb][kseg + 1][rowA] = av.y;
            As[nb][kseg + 2][rowA] = av.z;
            As[nb][kseg + 3][rowA] = av.w;
            Bs[nb][kseg + 0][rowA] = bv.x;
            Bs[nb][kseg + 1][rowA] = bv.y;
            Bs[nb][kseg + 2][rowA] = bv.z;
            Bs[nb][kseg + 3][rowA] = bv.w;
            __syncthreads();
        }
    }

    int ecap = e * CAP;
#pragma unroll
    for (int mi = 0; mi < 8; mi++) {
        int slot = m0 + ty * 8 + mi;
        if (slot >= cnt) continue;
        float* orow = g_O + (size_t)(ecap + slot) * DOUTS + n0 + tx * 8;
        float4 v0, v1;
        v0.x = acc[mi][0]; v0.y = acc[mi][1]; v0.z = acc[mi][2]; v0.w = acc[mi][3];
        v1.x = acc[mi][4]; v1.y = acc[mi][5]; v1.z = acc[mi][6]; v1.w = acc[mi][7];
        *(float4*)orow       = v0;
        *(float4*)(orow + 4) = v1;
    }
}

// ---------------- final combine ---------------------------------------------
__global__ void combine_kernel(float* __restrict__ out) {
    int i = blockIdx.x * blockDim.x + threadIdx.x;  // over TS*DOUTS/4
    if (i >= TS * (DOUTS / 4)) return;
    int t  = i / (DOUTS / 4);
    int d4 = i % (DOUTS / 4);
    const float4* O4 = (const float4*)g_O;
    float4 a = O4[(size_t)g_slot0[t] * (DOUTS / 4) + d4];
    int s1 = g_slot1[t];
    if (s1 >= 0) {
        float4 b = O4[(size_t)s1 * (DOUTS / 4) + d4];
        a.x += b.x; a.y += b.y; a.z += b.z; a.w += b.w;
    }
    ((float4*)out)[i] = a;
}

// ---------------- launch -----------------------------------------------------
extern "C" void kernel_launch(void* const* d_in, const int* in_sizes, int n_in,
                              void* d_out, int out_size) {
    const float* X   = (const float*)d_in[0];   // [T, D]
    const int*   idx = (const int*)d_in[1];     // [T, K] int32 (JAX default)
    const float* wts = (const float*)d_in[2];   // [T, K]
    const float* Wg  = (const float*)d_in[3];   // [E, H, D]
    const float* Wu  = (const float*)d_in[4];   // [E, H, D]
    const float* Wd  = (const float*)d_in[5];   // [E, DOUT, H]
    float* out = (float*)d_out;                 // [T, DOUT]

    zero_cnt_kernel<<<1, 32>>>();
    build_kernel<<<(TS + 255) / 256, 256>>>(idx, wts);

    dim3 gUp(CAP / 128, HS / 64, ES);           // 64 x 32 x 8 (early-exit on count)
    gateup_kernel<<<gUp, 256>>>(X, Wg, Wu);

    dim3 gDn(CAP / 128, DOUTS / 128, ES);       // 64 x 8 x 8
    down_kernel<<<gDn, 256>>>(Wd);

    combine_kernel<<<(TS * (DOUTS / 4) + 255) / 256, 256>>>(out);
}

// round 13
// speedup vs baseline: 1.2878x; 1.2867x over previous
#include <cuda_runtime.h>
#include <cuda_bf16.h>
#include <mma.h>
#include <math.h>

using namespace nvcuda;

// Problem constants
#define ES    8
#define DS    1024
#define HS    2048
#define DOUTS 1024
#define TS    8192
#define CAP   8192

// ---------------- scratch (device globals; allocations banned) ----------
__device__ int   g_cnt[ES];
__device__ int   g_tok[ES * CAP];
__device__ float g_wt [ES * CAP];
__device__ int   g_slot0[TS];
__device__ int   g_slot1[TS];
__device__ float g_Hb[(size_t)ES * CAP * HS];    // h = silu(g)*u*w  (512 MB)
__device__ float g_O[(size_t)ES * CAP * DOUTS];  // down proj output (256 MB)

// ---------------- bf16 hi/lo split (pure scalar integer math) ----------------
__device__ __forceinline__ unsigned int bf16rn(float x) {
    unsigned int b = __float_as_uint(x);
    return (b + 0x7FFFu + ((b >> 16) & 1u)) >> 16;
}
__device__ __forceinline__ void split2pack(float x0, float x1,
                                           unsigned int& hp, unsigned int& lp) {
    unsigned int h0 = bf16rn(x0);
    float r0 = x0 - __uint_as_float(h0 << 16);
    unsigned int l0 = bf16rn(r0);
    unsigned int h1 = bf16rn(x1);
    float r1 = x1 - __uint_as_float(h1 << 16);
    unsigned int l1 = bf16rn(r1);
    hp = h0 | (h1 << 16);
    lp = l0 | (l1 << 16);
}

// ---------------- routing ----------------------------------------------------
__global__ void zero_cnt_kernel() {
    if (threadIdx.x < ES) g_cnt[threadIdx.x] = 0;
}

__global__ void build_kernel(const int* __restrict__ idx,
                             const float* __restrict__ w) {
    int t = blockIdx.x * blockDim.x + threadIdx.x;
    if (t >= TS) return;
    int e0 = idx[2 * t];
    int e1 = idx[2 * t + 1];
    float w0 = w[2 * t];
    float w1 = w[2 * t + 1];
    if ((unsigned)e0 >= ES) e0 = 0;
    if ((unsigned)e1 >= ES) e1 = 0;
    if (e0 == e1) {
        int s = atomicAdd(&g_cnt[e0], 1);
        g_tok[e0 * CAP + s] = t;
        g_wt [e0 * CAP + s] = w0 + w1;
        g_slot0[t] = e0 * CAP + s;
        g_slot1[t] = -1;
    } else {
        int s0 = atomicAdd(&g_cnt[e0], 1);
        g_tok[e0 * CAP + s0] = t;
        g_wt [e0 * CAP + s0] = w0;
        int s1 = atomicAdd(&g_cnt[e1], 1);
        g_tok[e1 * CAP + s1] = t;
        g_wt [e1 * CAP + s1] = w1;
        g_slot0[t] = e0 * CAP + s0;
        g_slot1[t] = e1 * CAP + s1;
    }
}

// ---------------- fused gate+up GEMM (wmma bf16 3-term split) ----------------
// CTA tile: 128 gathered rows x 64 H-cols. K-tile = 16 fp32 (split in-kernel).
// Warps 4(m) x 2(n); warp tile 32x32 for each of g and u.
__global__ void gateup_kernel(const float* __restrict__ X,
                              const float* __restrict__ Wg,
                              const float* __restrict__ Wu) {
    __shared__ unsigned int sAhi[2][128][8], sAlo[2][128][8];
    __shared__ unsigned int sBghi[2][64][8], sBglo[2][64][8];
    __shared__ unsigned int sBuhi[2][64][8], sBulo[2][64][8];
    __shared__ float stg[8][256];      // per-warp 16x16 f32 staging

    int e = blockIdx.z;
    int cnt = g_cnt[e];
    int m0 = blockIdx.x * 128;
    if (m0 >= cnt) return;
    int n0 = blockIdx.y * 64;

    int tid = threadIdx.x;
    int wid = tid >> 5, lane = tid & 31;
    int wm = wid & 3, wn = wid >> 2;

    // loader mapping
    int rowA = tid >> 1;
    int kA = (tid & 1) * 8;            // 8 fp32 per thread for A
    int slotA = m0 + rowA;
    int token = (slotA < cnt) ? g_tok[e * CAP + slotA] : 0;
    const float* Arow = X + (size_t)token * DS;

    int rowB = (tid & 127) >> 1;
    int kB = (tid & 1) * 8;
    bool doU = (tid >= 128);
    const float* Brow = (doU ? Wu : Wg) + ((size_t)e * HS + n0 + rowB) * DS;

    wmma::fragment<wmma::accumulator, 16, 16, 16, float> accg[2][2], accu[2][2];
#pragma unroll
    for (int mi = 0; mi < 2; mi++)
#pragma unroll
        for (int ni = 0; ni < 2; ni++) {
            wmma::fill_fragment(accg[mi][ni], 0.0f);
            wmma::fill_fragment(accu[mi][ni], 0.0f);
        }

    // prime: load tile 0 into regs, split+store to buf 0
    float4 fa0 = *(const float4*)(Arow + kA);
    float4 fa1 = *(const float4*)(Arow + kA + 4);
    float4 fb0 = *(const float4*)(Brow + kB);
    float4 fb1 = *(const float4*)(Brow + kB + 4);
    {
        int ia = (tid & 1) * 4;
        unsigned int hp, lp;
        split2pack(fa0.x, fa0.y, hp, lp); sAhi[0][rowA][ia + 0] = hp; sAlo[0][rowA][ia + 0] = lp;
        split2pack(fa0.z, fa0.w, hp, lp); sAhi[0][rowA][ia + 1] = hp; sAlo[0][rowA][ia + 1] = lp;
        split2pack(fa1.x, fa1.y, hp, lp); sAhi[0][rowA][ia + 2] = hp; sAlo[0][rowA][ia + 2] = lp;
        split2pack(fa1.z, fa1.w, hp, lp); sAhi[0][rowA][ia + 3] = hp; sAlo[0][rowA][ia + 3] = lp;
        unsigned int (*bh)[8] = doU ? sBuhi[0] : sBghi[0];
        unsigned int (*bl)[8] = doU ? sBulo[0] : sBglo[0];
        split2pack(fb0.x, fb0.y, hp, lp); bh[rowB][ia + 0] = hp; bl[rowB][ia + 0] = lp;
        split2pack(fb0.z, fb0.w, hp, lp); bh[rowB][ia + 1] = hp; bl[rowB][ia + 1] = lp;
        split2pack(fb1.x, fb1.y, hp, lp); bh[rowB][ia + 2] = hp; bl[rowB][ia + 2] = lp;
        split2pack(fb1.z, fb1.w, hp, lp); bh[rowB][ia + 3] = hp; bl[rowB][ia + 3] = lp;
    }
    __syncthreads();

    const int NKT = DS / 16;  // 64
    for (int kt = 0; kt < NKT; kt++) {
        int buf = kt & 1;
        if (kt + 1 < NKT) {
            int kg = (kt + 1) * 16;
            fa0 = *(const float4*)(Arow + kg + kA);
            fa1 = *(const float4*)(Arow + kg + kA + 4);
            fb0 = *(const float4*)(Brow + kg + kB);
            fb1 = *(const float4*)(Brow + kg + kB + 4);
        }

        // compute from buf
        wmma::fragment<wmma::matrix_a, 16, 16, 16, __nv_bfloat16, wmma::row_major> fahi[2], falo[2];
#pragma unroll
        for (int mi = 0; mi < 2; mi++) {
            wmma::load_matrix_sync(fahi[mi], (const __nv_bfloat16*)&sAhi[buf][wm * 32 + mi * 16][0], 16);
            wmma::load_matrix_sync(falo[mi], (const __nv_bfloat16*)&sAlo[buf][wm * 32 + mi * 16][0], 16);
        }
#pragma unroll
        for (int ni = 0; ni < 2; ni++) {
            wmma::fragment<wmma::matrix_b, 16, 16, 16, __nv_bfloat16, wmma::col_major> fbgh, fbgl, fbuh, fbul;
            int nrow = wn * 32 + ni * 16;
            wmma::load_matrix_sync(fbgh, (const __nv_bfloat16*)&sBghi[buf][nrow][0], 16);
            wmma::load_matrix_sync(fbgl, (const __nv_bfloat16*)&sBglo[buf][nrow][0], 16);
            wmma::load_matrix_sync(fbuh, (const __nv_bfloat16*)&sBuhi[buf][nrow][0], 16);
            wmma::load_matrix_sync(fbul, (const __nv_bfloat16*)&sBulo[buf][nrow][0], 16);
#pragma unroll
            for (int mi = 0; mi < 2; mi++) {
                wmma::mma_sync(accg[mi][ni], fahi[mi], fbgh, accg[mi][ni]);
                wmma::mma_sync(accg[mi][ni], fahi[mi], fbgl, accg[mi][ni]);
                wmma::mma_sync(accg[mi][ni], falo[mi], fbgh, accg[mi][ni]);
                wmma::mma_sync(accu[mi][ni], fahi[mi], fbuh, accu[mi][ni]);
                wmma::mma_sync(accu[mi][ni], fahi[mi], fbul, accu[mi][ni]);
                wmma::mma_sync(accu[mi][ni], falo[mi], fbuh, accu[mi][ni]);
            }
        }

        // store prefetched tile into other buffer
        if (kt + 1 < NKT) {
            int nb = buf ^ 1;
            int ia = (tid & 1) * 4;
            unsigned int hp, lp;
            split2pack(fa0.x, fa0.y, hp, lp); sAhi[nb][rowA][ia + 0] = hp; sAlo[nb][rowA][ia + 0] = lp;
            split2pack(fa0.z, fa0.w, hp, lp); sAhi[nb][rowA][ia + 1] = hp; sAlo[nb][rowA][ia + 1] = lp;
            split2pack(fa1.x, fa1.y, hp, lp); sAhi[nb][rowA][ia + 2] = hp; sAlo[nb][rowA][ia + 2] = lp;
            split2pack(fa1.z, fa1.w, hp, lp); sAhi[nb][rowA][ia + 3] = hp; sAlo[nb][rowA][ia + 3] = lp;
            unsigned int (*bh)[8] = doU ? sBuhi[nb] : sBghi[nb];
            unsigned int (*bl)[8] = doU ? sBulo[nb] : sBglo[nb];
            split2pack(fb0.x, fb0.y, hp, lp); bh[rowB][ia + 0] = hp; bl[rowB][ia + 0] = lp;
            split2pack(fb0.z, fb0.w, hp, lp); bh[rowB][ia + 1] = hp; bl[rowB][ia + 1] = lp;
            split2pack(fb1.x, fb1.y, hp, lp); bh[rowB][ia + 2] = hp; bl[rowB][ia + 2] = lp;
            split2pack(fb1.z, fb1.w, hp, lp); bh[rowB][ia + 3] = hp; bl[rowB][ia + 3] = lp;
            __syncthreads();
        }
    }

    // epilogue: stage g then u through shared, fuse silu(g)*u*w -> g_Hb
    int ecap = e * CAP;
    int r = lane >> 1, c0 = (lane & 1) * 8;
#pragma unroll
    for (int mi = 0; mi < 2; mi++)
#pragma unroll
        for (int ni = 0; ni < 2; ni++) {
            wmma::store_matrix_sync(&stg[wid][0], accg[mi][ni], 16, wmma::mem_row_major);
            __syncwarp();
            float4 gv0 = *(const float4*)&stg[wid][r * 16 + c0];
            float4 gv1 = *(const float4*)&stg[wid][r * 16 + c0 + 4];
            __syncwarp();
            wmma::store_matrix_sync(&stg[wid][0], accu[mi][ni], 16, wmma::mem_row_major);
            __syncwarp();
            float4 uv0 = *(const float4*)&stg[wid][r * 16 + c0];
            float4 uv1 = *(const float4*)&stg[wid][r * 16 + c0 + 4];
            __syncwarp();
            int slot = m0 + wm * 32 + mi * 16 + r;
            if (slot < cnt) {
                float wv = g_wt[ecap + slot];
                float* hr = g_Hb + (size_t)(ecap + slot) * HS + n0 + wn * 32 + ni * 16 + c0;
                float4 o0, o1;
                o0.x = (gv0.x / (1.0f + __expf(-gv0.x))) * uv0.x * wv;
                o0.y = (gv0.y / (1.0f + __expf(-gv0.y))) * uv0.y * wv;
                o0.z = (gv0.z / (1.0f + __expf(-gv0.z))) * uv0.z * wv;
                o0.w = (gv0.w / (1.0f + __expf(-gv0.w))) * uv0.w * wv;
                o1.x = (gv1.x / (1.0f + __expf(-gv1.x))) * uv1.x * wv;
                o1.y = (gv1.y / (1.0f + __expf(-gv1.y))) * uv1.y * wv;
                o1.z = (gv1.z / (1.0f + __expf(-gv1.z))) * uv1.z * wv;
                o1.w = (gv1.w / (1.0f + __expf(-gv1.w))) * uv1.w * wv;
                *(float4*)hr       = o0;
                *(float4*)(hr + 4) = o1;
            }
        }
}

// ---------------- down GEMM: O = H @ Wd^T (wmma bf16 3-term split) -----------
// CTA tile: 128 rows x 64 DOUT-cols. K-tile 16 over HS=2048.
__global__ void down_kernel(const float* __restrict__ Wd) {
    __shared__ unsigned int sAhi[2][128][8], sAlo[2][128][8];
    __shared__ unsigned int sBhi[2][64][8], sBlo[2][64][8];

    int e = blockIdx.z;
    int cnt = g_cnt[e];
    int m0 = blockIdx.x * 128;
    if (m0 >= cnt) return;
    int n0 = blockIdx.y * 64;

    int tid = threadIdx.x;
    int wid = tid >> 5;
    int wm = wid & 3, wn = wid >> 2;

    int rowA = tid >> 1;
    int kA = (tid & 1) * 8;
    const float* Arow = g_Hb + (size_t)(e * CAP + m0 + rowA) * HS;

    int rowB = tid >> 2;                 // 0..63
    int kB = (tid & 3) * 4;              // 4 fp32 per thread for B
    const float* Brow = Wd + ((size_t)e * DOUTS + n0 + rowB) * HS;

    wmma::fragment<wmma::accumulator, 16, 16, 16, float> acc[2][2];
#pragma unroll
    for (int mi = 0; mi < 2; mi++)
#pragma unroll
        for (int ni = 0; ni < 2; ni++)
            wmma::fill_fragment(acc[mi][ni], 0.0f);

    float4 fa0 = *(const float4*)(Arow + kA);
    float4 fa1 = *(const float4*)(Arow + kA + 4);
    float4 fb0 = *(const float4*)(Brow + kB);
    {
        int ia = (tid & 1) * 4;
        int ib = (tid & 3) * 2;
        unsigned int hp, lp;
        split2pack(fa0.x, fa0.y, hp, lp); sAhi[0][rowA][ia + 0] = hp; sAlo[0][rowA][ia + 0] = lp;
        split2pack(fa0.z, fa0.w, hp, lp); sAhi[0][rowA][ia + 1] = hp; sAlo[0][rowA][ia + 1] = lp;
        split2pack(fa1.x, fa1.y, hp, lp); sAhi[0][rowA][ia + 2] = hp; sAlo[0][rowA][ia + 2] = lp;
        split2pack(fa1.z, fa1.w, hp, lp); sAhi[0][rowA][ia + 3] = hp; sAlo[0][rowA][ia + 3] = lp;
        split2pack(fb0.x, fb0.y, hp, lp); sBhi[0][rowB][ib + 0] = hp; sBlo[0][rowB][ib + 0] = lp;
        split2pack(fb0.z, fb0.w, hp, lp); sBhi[0][rowB][ib + 1] = hp; sBlo[0][rowB][ib + 1] = lp;
    }
    __syncthreads();

    const int NKT = HS / 16;  // 128
    for (int kt = 0; kt < NKT; kt++) {
        int buf = kt & 1;
        if (kt + 1 < NKT) {
            int kg = (kt + 1) * 16;
            fa0 = *(const float4*)(Arow + kg + kA);
            fa1 = *(const float4*)(Arow + kg + kA + 4);
            fb0 = *(const float4*)(Brow + kg + kB);
        }

        wmma::fragment<wmma::matrix_a, 16, 16, 16, __nv_bfloat16, wmma::row_major> fahi[2], falo[2];
#pragma unroll
        for (int mi = 0; mi < 2; mi++) {
            wmma::load_matrix_sync(fahi[mi], (const __nv_bfloat16*)&sAhi[buf][wm * 32 + mi * 16][0], 16);
            wmma::load_matrix_sync(falo[mi], (const __nv_bfloat16*)&sAlo[buf][wm * 32 + mi * 16][0], 16);
        }
#pragma unroll
        for (int ni = 0; ni < 2; ni++) {
            wmma::fragment<wmma::matrix_b, 16, 16, 16, __nv_bfloat16, wmma::col_major> fbh, fbl;
            int nrow = wn * 32 + ni * 16;
            wmma::load_matrix_sync(fbh, (const __nv_bfloat16*)&sBhi[buf][nrow][0], 16);
            wmma::load_matrix_sync(fbl, (const __nv_bfloat16*)&sBlo[buf][nrow][0], 16);
#pragma unroll
            for (int mi = 0; mi < 2; mi++) {
                wmma::mma_sync(acc[mi][ni], fahi[mi], fbh, acc[mi][ni]);
                wmma::mma_sync(acc[mi][ni], fahi[mi], fbl, acc[mi][ni]);
                wmma::mma_sync(acc[mi][ni], falo[mi], fbh, acc[mi][ni]);
            }
        }

        if (kt + 1 < NKT) {
            int nb = buf ^ 1;
            int ia = (tid & 1) * 4;
            int ib = (tid & 3) * 2;
            unsigned int hp, lp;
            split2pack(fa0.x, fa0.y, hp, lp); sAhi[nb][rowA][ia + 0] = hp; sAlo[nb][rowA][ia + 0] = lp;
            split2pack(fa0.z, fa0.w, hp, lp); sAhi[nb][rowA][ia + 1] = hp; sAlo[nb][rowA][ia + 1] = lp;
            split2pack(fa1.x, fa1.y, hp, lp); sAhi[nb][rowA][ia + 2] = hp; sAlo[nb][rowA][ia + 2] = lp;
            split2pack(fa1.z, fa1.w, hp, lp); sAhi[nb][rowA][ia + 3] = hp; sAlo[nb][rowA][ia + 3] = lp;
            split2pack(fb0.x, fb0.y, hp, lp); sBhi[nb][rowB][ib + 0] = hp; sBlo[nb][rowB][ib + 0] = lp;
            split2pack(fb0.z, fb0.w, hp, lp); sBhi[nb][rowB][ib + 1] = hp; sBlo[nb][rowB][ib + 1] = lp;
            __syncthreads();
        }
    }

    // epilogue: direct wmma store to global (unused rows harmless, never read)
    int ecap = e * CAP;
#pragma unroll
    for (int mi = 0; mi < 2; mi++)
#pragma unroll
        for (int ni = 0; ni < 2; ni++) {
            float* dst = g_O + (size_t)(ecap + m0 + wm * 32 + mi * 16) * DOUTS
                       + n0 + wn * 32 + ni * 16;
            wmma::store_matrix_sync(dst, acc[mi][ni], DOUTS, wmma::mem_row_major);
        }
}

// ---------------- final combine ---------------------------------------------
__global__ void combine_kernel(float* __restrict__ out) {
    int i = blockIdx.x * blockDim.x + threadIdx.x;  // over TS*DOUTS/4
    if (i >= TS * (DOUTS / 4)) return;
    int t  = i / (DOUTS / 4);
    int d4 = i % (DOUTS / 4);
    const float4* O4 = (const float4*)g_O;
    float4 a = O4[(size_t)g_slot0[t] * (DOUTS / 4) + d4];
    int s1 = g_slot1[t];
    if (s1 >= 0) {
        float4 b = O4[(size_t)s1 * (DOUTS / 4) + d4];
        a.x += b.x; a.y += b.y; a.z += b.z; a.w += b.w;
    }
    ((float4*)out)[i] = a;
}

// ---------------- launch -----------------------------------------------------
extern "C" void kernel_launch(void* const* d_in, const int* in_sizes, int n_in,
                              void* d_out, int out_size) {
    const float* X   = (const float*)d_in[0];   // [T, D]
    const int*   idx = (const int*)d_in[1];     // [T, K] int32 (JAX default)
    const float* wts = (const float*)d_in[2];   // [T, K]
    const float* Wg  = (const float*)d_in[3];   // [E, H, D]
    const float* Wu  = (const float*)d_in[4];   // [E, H, D]
    const float* Wd  = (const float*)d_in[5];   // [E, DOUT, H]
    float* out = (float*)d_out;                 // [T, DOUT]

    zero_cnt_kernel<<<1, 32>>>();
    build_kernel<<<(TS + 255) / 256, 256>>>(idx, wts);

    dim3 gUp(CAP / 128, HS / 64, ES);           // 64 x 32 x 8 (early-exit on count)
    gateup_kernel<<<gUp, 256>>>(X, Wg, Wu);

    dim3 gDn(CAP / 128, DOUTS / 64, ES);        // 64 x 16 x 8
    down_kernel<<<gDn, 256>>>(Wd);

    combine_kernel<<<(TS * (DOUTS / 4) + 255) / 256, 256>>>(out);
}

// round 16
// speedup vs baseline: 1.3790x; 1.0708x over previous
#include <cuda_runtime.h>
#include <cuda_bf16.h>
#include <mma.h>
#include <math.h>

using namespace nvcuda;

// Problem constants
#define ES    8
#define DS    1024
#define HS    2048
#define DOUTS 1024
#define TS    8192
#define CAP   8192

// ---------------- scratch (device globals; allocations banned) ----------
__device__ int   g_cnt[ES];
__device__ int   g_tok[ES * CAP];
__device__ float g_wt [ES * CAP];
__device__ int   g_slot0[TS];
__device__ int   g_slot1[TS];

// H stored pre-split as bf16 hi/lo images (u16). Total = 512 MiB (same as old g_Hb).
__device__ unsigned short g_Hhi[(size_t)ES * CAP * HS];
__device__ unsigned short g_Hlo[(size_t)ES * CAP * HS];
__device__ float g_O[(size_t)ES * CAP * DOUTS];  // 256 MiB

// ---------------- bf16 hi/lo split (pure scalar integer math) ----------------
__device__ __forceinline__ unsigned int bf16rn(float x) {
    unsigned int b = __float_as_uint(x);
    return (b + 0x7FFFu + ((b >> 16) & 1u)) >> 16;
}
__device__ __forceinline__ void split2pack(float x0, float x1,
                                           unsigned int& hp, unsigned int& lp) {
    unsigned int h0 = bf16rn(x0);
    float r0 = x0 - __uint_as_float(h0 << 16);
    unsigned int l0 = bf16rn(r0);
    unsigned int h1 = bf16rn(x1);
    float r1 = x1 - __uint_as_float(h1 << 16);
    unsigned int l1 = bf16rn(r1);
    hp = h0 | (h1 << 16);
    lp = l0 | (l1 << 16);
}

// ---------------- routing ----------------------------------------------------
__global__ void zero_cnt_kernel() {
    if (threadIdx.x < ES) g_cnt[threadIdx.x] = 0;
}

__global__ void build_kernel(const int* __restrict__ idx,
                             const float* __restrict__ w) {
    int t = blockIdx.x * blockDim.x + threadIdx.x;
    if (t >= TS) return;
    int e0 = idx[2 * t];
    int e1 = idx[2 * t + 1];
    float w0 = w[2 * t];
    float w1 = w[2 * t + 1];
    if ((unsigned)e0 >= ES) e0 = 0;
    if ((unsigned)e1 >= ES) e1 = 0;
    if (e0 == e1) {
        int s = atomicAdd(&g_cnt[e0], 1);
        g_tok[e0 * CAP + s] = t;
        g_wt [e0 * CAP + s] = w0 + w1;
        g_slot0[t] = e0 * CAP + s;
        g_slot1[t] = -1;
    } else {
        int s0 = atomicAdd(&g_cnt[e0], 1);
        g_tok[e0 * CAP + s0] = t;
        g_wt [e0 * CAP + s0] = w0;
        int s1 = atomicAdd(&g_cnt[e1], 1);
        g_tok[e1 * CAP + s1] = t;
        g_wt [e1 * CAP + s1] = w1;
        g_slot0[t] = e0 * CAP + s0;
        g_slot1[t] = e1 * CAP + s1;
    }
}

// ---------------- fused gate+up GEMM (wmma bf16 3-term split) ----------------
// CTA tile: 128 gathered rows x 64 H-cols. K-tile = 16 fp32 (split in-kernel).
// Warps 4(m) x 2(n); warp tile 32x32 for each of g and u.   [R13-identical
// mainloop; epilogue now emits pre-split bf16 hi/lo H images]
__global__ void gateup_kernel(const float* __restrict__ X,
                              const float* __restrict__ Wg,
                              const float* __restrict__ Wu,
                              const int* __restrict__ dummy) {
    __shared__ unsigned int sAhi[2][128][8], sAlo[2][128][8];
    __shared__ unsigned int sBghi[2][64][8], sBglo[2][64][8];
    __shared__ unsigned int sBuhi[2][64][8], sBulo[2][64][8];
    __shared__ float stg[8][256];      // per-warp 16x16 f32 staging

    int e = blockIdx.z;
    int cnt = g_cnt[e];
    int m0 = blockIdx.x * 128;
    if (m0 >= cnt) return;
    int n0 = blockIdx.y * 64;

    int tid = threadIdx.x;
    int wid = tid >> 5, lane = tid & 31;
    int wm = wid & 3, wn = wid >> 2;

    // loader mapping
    int rowA = tid >> 1;
    int kA = (tid & 1) * 8;            // 8 fp32 per thread for A
    int slotA = m0 + rowA;
    int token = (slotA < cnt) ? g_tok[e * CAP + slotA] : 0;
    const float* Arow = X + (size_t)token * DS;

    int rowB = (tid & 127) >> 1;
    int kB = (tid & 1) * 8;
    bool doU = (tid >= 128);
    const float* Brow = (doU ? Wu : Wg) + ((size_t)e * HS + n0 + rowB) * DS;

    wmma::fragment<wmma::accumulator, 16, 16, 16, float> accg[2][2], accu[2][2];
#pragma unroll
    for (int mi = 0; mi < 2; mi++)
#pragma unroll
        for (int ni = 0; ni < 2; ni++) {
            wmma::fill_fragment(accg[mi][ni], 0.0f);
            wmma::fill_fragment(accu[mi][ni], 0.0f);
        }

    // prime: load tile 0 into regs, split+store to buf 0
    float4 fa0 = *(const float4*)(Arow + kA);
    float4 fa1 = *(const float4*)(Arow + kA + 4);
    float4 fb0 = *(const float4*)(Brow + kB);
    float4 fb1 = *(const float4*)(Brow + kB + 4);
    {
        int ia = (tid & 1) * 4;
        unsigned int hp, lp;
        split2pack(fa0.x, fa0.y, hp, lp); sAhi[0][rowA][ia + 0] = hp; sAlo[0][rowA][ia + 0] = lp;
        split2pack(fa0.z, fa0.w, hp, lp); sAhi[0][rowA][ia + 1] = hp; sAlo[0][rowA][ia + 1] = lp;
        split2pack(fa1.x, fa1.y, hp, lp); sAhi[0][rowA][ia + 2] = hp; sAlo[0][rowA][ia + 2] = lp;
        split2pack(fa1.z, fa1.w, hp, lp); sAhi[0][rowA][ia + 3] = hp; sAlo[0][rowA][ia + 3] = lp;
        unsigned int (*bh)[8] = doU ? sBuhi[0] : sBghi[0];
        unsigned int (*bl)[8] = doU ? sBulo[0] : sBglo[0];
        split2pack(fb0.x, fb0.y, hp, lp); bh[rowB][ia + 0] = hp; bl[rowB][ia + 0] = lp;
        split2pack(fb0.z, fb0.w, hp, lp); bh[rowB][ia + 1] = hp; bl[rowB][ia + 1] = lp;
        split2pack(fb1.x, fb1.y, hp, lp); bh[rowB][ia + 2] = hp; bl[rowB][ia + 2] = lp;
        split2pack(fb1.z, fb1.w, hp, lp); bh[rowB][ia + 3] = hp; bl[rowB][ia + 3] = lp;
    }
    __syncthreads();

    const int NKT = DS / 16;  // 64
    for (int kt = 0; kt < NKT; kt++) {
        int buf = kt & 1;
        if (kt + 1 < NKT) {
            int kg = (kt + 1) * 16;
            fa0 = *(const float4*)(Arow + kg + kA);
            fa1 = *(const float4*)(Arow + kg + kA + 4);
            fb0 = *(const float4*)(Brow + kg + kB);
            fb1 = *(const float4*)(Brow + kg + kB + 4);
        }

        wmma::fragment<wmma::matrix_a, 16, 16, 16, __nv_bfloat16, wmma::row_major> fahi[2], falo[2];
#pragma unroll
        for (int mi = 0; mi < 2; mi++) {
            wmma::load_matrix_sync(fahi[mi], (const __nv_bfloat16*)&sAhi[buf][wm * 32 + mi * 16][0], 16);
            wmma::load_matrix_sync(falo[mi], (const __nv_bfloat16*)&sAlo[buf][wm * 32 + mi * 16][0], 16);
        }
#pragma unroll
        for (int ni = 0; ni < 2; ni++) {
            wmma::fragment<wmma::matrix_b, 16, 16, 16, __nv_bfloat16, wmma::col_major> fbgh, fbgl, fbuh, fbul;
            int nrow = wn * 32 + ni * 16;
            wmma::load_matrix_sync(fbgh, (const __nv_bfloat16*)&sBghi[buf][nrow][0], 16);
            wmma::load_matrix_sync(fbgl, (const __nv_bfloat16*)&sBglo[buf][nrow][0], 16);
            wmma::load_matrix_sync(fbuh, (const __nv_bfloat16*)&sBuhi[buf][nrow][0], 16);
            wmma::load_matrix_sync(fbul, (const __nv_bfloat16*)&sBulo[buf][nrow][0], 16);
#pragma unroll
            for (int mi = 0; mi < 2; mi++) {
                wmma::mma_sync(accg[mi][ni], fahi[mi], fbgh, accg[mi][ni]);
                wmma::mma_sync(accg[mi][ni], fahi[mi], fbgl, accg[mi][ni]);
                wmma::mma_sync(accg[mi][ni], falo[mi], fbgh, accg[mi][ni]);
                wmma::mma_sync(accu[mi][ni], fahi[mi], fbuh, accu[mi][ni]);
                wmma::mma_sync(accu[mi][ni], fahi[mi], fbul, accu[mi][ni]);
                wmma::mma_sync(accu[mi][ni], falo[mi], fbuh, accu[mi][ni]);
            }
        }

        if (kt + 1 < NKT) {
            int nb = buf ^ 1;
            int ia = (tid & 1) * 4;
            unsigned int hp, lp;
            split2pack(fa0.x, fa0.y, hp, lp); sAhi[nb][rowA][ia + 0] = hp; sAlo[nb][rowA][ia + 0] = lp;
            split2pack(fa0.z, fa0.w, hp, lp); sAhi[nb][rowA][ia + 1] = hp; sAlo[nb][rowA][ia + 1] = lp;
            split2pack(fa1.x, fa1.y, hp, lp); sAhi[nb][rowA][ia + 2] = hp; sAlo[nb][rowA][ia + 2] = lp;
            split2pack(fa1.z, fa1.w, hp, lp); sAhi[nb][rowA][ia + 3] = hp; sAlo[nb][rowA][ia + 3] = lp;
            unsigned int (*bh)[8] = doU ? sBuhi[nb] : sBghi[nb];
            unsigned int (*bl)[8] = doU ? sBulo[nb] : sBglo[nb];
            split2pack(fb0.x, fb0.y, hp, lp); bh[rowB][ia + 0] = hp; bl[rowB][ia + 0] = lp;
            split2pack(fb0.z, fb0.w, hp, lp); bh[rowB][ia + 1] = hp; bl[rowB][ia + 1] = lp;
            split2pack(fb1.x, fb1.y, hp, lp); bh[rowB][ia + 2] = hp; bl[rowB][ia + 2] = lp;
            split2pack(fb1.z, fb1.w, hp, lp); bh[rowB][ia + 3] = hp; bl[rowB][ia + 3] = lp;
            __syncthreads();
        }
    }

    // epilogue: silu(g)*u*w, split, element-wise u32 stores to hi/lo H images
    int ecap = e * CAP;
    int r = lane >> 1, c0 = (lane & 1) * 8;
#pragma unroll
    for (int mi = 0; mi < 2; mi++)
#pragma unroll
        for (int ni = 0; ni < 2; ni++) {
            wmma::store_matrix_sync(&stg[wid][0], accg[mi][ni], 16, wmma::mem_row_major);
            __syncwarp();
            float4 gv0 = *(const float4*)&stg[wid][r * 16 + c0];
            float4 gv1 = *(const float4*)&stg[wid][r * 16 + c0 + 4];
            __syncwarp();
            wmma::store_matrix_sync(&stg[wid][0], accu[mi][ni], 16, wmma::mem_row_major);
            __syncwarp();
            float4 uv0 = *(const float4*)&stg[wid][r * 16 + c0];
            float4 uv1 = *(const float4*)&stg[wid][r * 16 + c0 + 4];
            __syncwarp();
            int slot = m0 + wm * 32 + mi * 16 + r;
            if (slot < cnt) {
                float wv = g_wt[ecap + slot];
                float o0 = (gv0.x / (1.0f + __expf(-gv0.x))) * uv0.x * wv;
                float o1 = (gv0.y / (1.0f + __expf(-gv0.y))) * uv0.y * wv;
                float o2 = (gv0.z / (1.0f + __expf(-gv0.z))) * uv0.z * wv;
                float o3 = (gv0.w / (1.0f + __expf(-gv0.w))) * uv0.w * wv;
                float o4 = (gv1.x / (1.0f + __expf(-gv1.x))) * uv1.x * wv;
                float o5 = (gv1.y / (1.0f + __expf(-gv1.y))) * uv1.y * wv;
                float o6 = (gv1.z / (1.0f + __expf(-gv1.z))) * uv1.z * wv;
                float o7 = (gv1.w / (1.0f + __expf(-gv1.w))) * uv1.w * wv;
                unsigned int hp0, lp0, hp1, lp1, hp2, lp2, hp3, lp3;
                split2pack(o0, o1, hp0, lp0);
                split2pack(o2, o3, hp1, lp1);
                split2pack(o4, o5, hp2, lp2);
                split2pack(o6, o7, hp3, lp3);
                size_t hoff = (size_t)(ecap + slot) * HS + n0 + wn * 32 + ni * 16 + c0;
                unsigned int* dh = (unsigned int*)(g_Hhi + hoff);
                unsigned int* dl = (unsigned int*)(g_Hlo + hoff);
                dh[0] = hp0; dh[1] = hp1; dh[2] = hp2; dh[3] = hp3;
                dl[0] = lp0; dl[1] = lp1; dl[2] = lp2; dl[3] = lp3;
            }
        }
}

// ---------------- down GEMM: O = H @ Wd^T (A pre-split, B split in-loop) -----
// CTA tile: 128 rows x 128 DOUT-cols. K-tile 16 over HS=2048.
// Warps 4(m) x 2(n); warp tile 32 x 64.
__global__ void down_kernel(const float* __restrict__ Wd) {
    __shared__ unsigned int sAhi[2][128][8], sAlo[2][128][8];
    __shared__ unsigned int sBhi[2][128][8], sBlo[2][128][8];

    int e = blockIdx.z;
    int cnt = g_cnt[e];
    int m0 = blockIdx.x * 128;
    if (m0 >= cnt) return;
    int n0 = blockIdx.y * 128;
    int ecap = e * CAP;

    int tid = threadIdx.x;
    int wid = tid >> 5;
    int wm = wid & 3, wn = wid >> 2;

    // A loader: pre-split images; row = tid>>1, seg = (tid&1)*8 (u16 elems)
    int rowA = tid >> 1, segA = (tid & 1) * 8;
    const unsigned short* Ahirow = g_Hhi + (size_t)(ecap + m0 + rowA) * HS + segA;
    const unsigned short* Alorow = g_Hlo + (size_t)(ecap + m0 + rowA) * HS + segA;

    // B loader: fp32 Wd, split in-loop; row = tid>>1, seg = (tid&1)*8 fp32
    int rowB = tid >> 1, kB = (tid & 1) * 8;
    const float* Brow = Wd + ((size_t)e * DOUTS + n0 + rowB) * HS + kB;

    wmma::fragment<wmma::accumulator, 16, 16, 16, float> acc[2][4];
#pragma unroll
    for (int mi = 0; mi < 2; mi++)
#pragma unroll
        for (int ni = 0; ni < 4; ni++)
            wmma::fill_fragment(acc[mi][ni], 0.0f);

    // prime
    uint4 pAh = *(const uint4*)(Ahirow);
    uint4 pAl = *(const uint4*)(Alorow);
    float4 fb0 = *(const float4*)(Brow);
    float4 fb1 = *(const float4*)(Brow + 4);
    {
        int ia = (tid & 1) * 4;
        sAhi[0][rowA][ia + 0] = pAh.x; sAhi[0][rowA][ia + 1] = pAh.y;
        sAhi[0][rowA][ia + 2] = pAh.z; sAhi[0][rowA][ia + 3] = pAh.w;
        sAlo[0][rowA][ia + 0] = pAl.x; sAlo[0][rowA][ia + 1] = pAl.y;
        sAlo[0][rowA][ia + 2] = pAl.z; sAlo[0][rowA][ia + 3] = pAl.w;
        unsigned int hp, lp;
        split2pack(fb0.x, fb0.y, hp, lp); sBhi[0][rowB][ia + 0] = hp; sBlo[0][rowB][ia + 0] = lp;
        split2pack(fb0.z, fb0.w, hp, lp); sBhi[0][rowB][ia + 1] = hp; sBlo[0][rowB][ia + 1] = lp;
        split2pack(fb1.x, fb1.y, hp, lp); sBhi[0][rowB][ia + 2] = hp; sBlo[0][rowB][ia + 2] = lp;
        split2pack(fb1.z, fb1.w, hp, lp); sBhi[0][rowB][ia + 3] = hp; sBlo[0][rowB][ia + 3] = lp;
    }
    __syncthreads();

    const int NKT = HS / 16;  // 128
    for (int kt = 0; kt < NKT; kt++) {
        int buf = kt & 1;
        if (kt + 1 < NKT) {
            int kg = (kt + 1) * 16;
            pAh = *(const uint4*)(Ahirow + kg);
            pAl = *(const uint4*)(Alorow + kg);
            fb0 = *(const float4*)(Brow + kg);
            fb1 = *(const float4*)(Brow + kg + 4);
        }

        wmma::fragment<wmma::matrix_a, 16, 16, 16, __nv_bfloat16, wmma::row_major> fahi[2], falo[2];
#pragma unroll
        for (int mi = 0; mi < 2; mi++) {
            wmma::load_matrix_sync(fahi[mi], (const __nv_bfloat16*)&sAhi[buf][wm * 32 + mi * 16][0], 16);
            wmma::load_matrix_sync(falo[mi], (const __nv_bfloat16*)&sAlo[buf][wm * 32 + mi * 16][0], 16);
        }
#pragma unroll
        for (int ni = 0; ni < 4; ni++) {
            wmma::fragment<wmma::matrix_b, 16, 16, 16, __nv_bfloat16, wmma::col_major> fbh, fbl;
            int nrow = wn * 64 + ni * 16;
            wmma::load_matrix_sync(fbh, (const __nv_bfloat16*)&sBhi[buf][nrow][0], 16);
            wmma::load_matrix_sync(fbl, (const __nv_bfloat16*)&sBlo[buf][nrow][0], 16);
#pragma unroll
            for (int mi = 0; mi < 2; mi++) {
                wmma::mma_sync(acc[mi][ni], fahi[mi], fbh, acc[mi][ni]);
                wmma::mma_sync(acc[mi][ni], fahi[mi], fbl, acc[mi][ni]);
                wmma::mma_sync(acc[mi][ni], falo[mi], fbh, acc[mi][ni]);
            }
        }

        if (kt + 1 < NKT) {
            int nb = buf ^ 1;
            int ia = (tid & 1) * 4;
            sAhi[nb][rowA][ia + 0] = pAh.x; sAhi[nb][rowA][ia + 1] = pAh.y;
            sAhi[nb][rowA][ia + 2] = pAh.z; sAhi[nb][rowA][ia + 3] = pAh.w;
            sAlo[nb][rowA][ia + 0] = pAl.x; sAlo[nb][rowA][ia + 1] = pAl.y;
            sAlo[nb][rowA][ia + 2] = pAl.z; sAlo[nb][rowA][ia + 3] = pAl.w;
            unsigned int hp, lp;
            split2pack(fb0.x, fb0.y, hp, lp); sBhi[nb][rowB][ia + 0] = hp; sBlo[nb][rowB][ia + 0] = lp;
            split2pack(fb0.z, fb0.w, hp, lp); sBhi[nb][rowB][ia + 1] = hp; sBlo[nb][rowB][ia + 1] = lp;
            split2pack(fb1.x, fb1.y, hp, lp); sBhi[nb][rowB][ia + 2] = hp; sBlo[nb][rowB][ia + 2] = lp;
            split2pack(fb1.z, fb1.w, hp, lp); sBhi[nb][rowB][ia + 3] = hp; sBlo[nb][rowB][ia + 3] = lp;
            __syncthreads();
        }
    }

    // epilogue: direct wmma store to global (unused rows harmless, never read)
#pragma unroll
    for (int mi = 0; mi < 2; mi++)
#pragma unroll
        for (int ni = 0; ni < 4; ni++) {
            float* dst = g_O + (size_t)(ecap + m0 + wm * 32 + mi * 16) * DOUTS
                       + n0 + wn * 64 + ni * 16;
            wmma::store_matrix_sync(dst, acc[mi][ni], DOUTS, wmma::mem_row_major);
        }
}

// ---------------- final combine ---------------------------------------------
__global__ void combine_kernel(float* __restrict__ out) {
    int i = blockIdx.x * blockDim.x + threadIdx.x;  // over TS*DOUTS/4
    if (i >= TS * (DOUTS / 4)) return;
    int t  = i / (DOUTS / 4);
    int d4 = i % (DOUTS / 4);
    const float4* O4 = (const float4*)g_O;
    float4 a = O4[(size_t)g_slot0[t] * (DOUTS / 4) + d4];
    int s1 = g_slot1[t];
    if (s1 >= 0) {
        float4 b = O4[(size_t)s1 * (DOUTS / 4) + d4];
        a.x += b.x; a.y += b.y; a.z += b.z; a.w += b.w;
    }
    ((float4*)out)[i] = a;
}

// ---------------- launch -----------------------------------------------------
extern "C" void kernel_launch(void* const* d_in, const int* in_sizes, int n_in,
                              void* d_out, int out_size) {
    const float* X   = (const float*)d_in[0];   // [T, D]
    const int*   idx = (const int*)d_in[1];     // [T, K] int32 (JAX default)
    const float* wts = (const float*)d_in[2];   // [T, K]
    const float* Wg  = (const float*)d_in[3];   // [E, H, D]
    const float* Wu  = (const float*)d_in[4];   // [E, H, D]
    const float* Wd  = (const float*)d_in[5];   // [E, DOUT, H]
    float* out = (float*)d_out;                 // [T, DOUT]

    zero_cnt_kernel<<<1, 32>>>();
    build_kernel<<<(TS + 255) / 256, 256>>>(idx, wts);

    dim3 gUp(CAP / 128, HS / 64, ES);           // 64 x 32 x 8 (early-exit on count)
    gateup_kernel<<<gUp, 256>>>(X, Wg, Wu, idx);

    dim3 gDn(CAP / 128, DOUTS / 128, ES);       // 64 x 8 x 8
    down_kernel<<<gDn, 256>>>(Wd);

    combine_kernel<<<(TS * (DOUTS / 4) + 255) / 256, 256>>>(out);
}

// round 17
// speedup vs baseline: 1.5432x; 1.1191x over previous
#include <cuda_runtime.h>
#include <cuda_bf16.h>
#include <mma.h>
#include <math.h>

using namespace nvcuda;

// Problem constants
#define ES    8
#define DS    1024
#define HS    2048
#define DOUTS 1024
#define TS    8192
#define CAP   8192

#define LDM   24     // smem leading dim in bf16 (48B rows: conflict-free ldmatrix)
#define LDW   12     // same, in u32 words

// ---------------- scratch (device globals; allocations banned) ----------
__device__ int   g_cnt[ES];
__device__ int   g_tok[ES * CAP];
__device__ float g_wt [ES * CAP];
__device__ int   g_slot0[TS];
__device__ int   g_slot1[TS];

// H stored pre-split as bf16 hi/lo images (u16). Total = 512 MiB.
__device__ unsigned short g_Hhi[(size_t)ES * CAP * HS];
__device__ unsigned short g_Hlo[(size_t)ES * CAP * HS];
__device__ float g_O[(size_t)ES * CAP * DOUTS];  // 256 MiB

// ---------------- bf16 hi/lo split (pure scalar integer math) ----------------
__device__ __forceinline__ unsigned int bf16rn(float x) {
    unsigned int b = __float_as_uint(x);
    return (b + 0x7FFFu + ((b >> 16) & 1u)) >> 16;
}
__device__ __forceinline__ void split2pack(float x0, float x1,
                                           unsigned int& hp, unsigned int& lp) {
    unsigned int h0 = bf16rn(x0);
    float r0 = x0 - __uint_as_float(h0 << 16);
    unsigned int l0 = bf16rn(r0);
    unsigned int h1 = bf16rn(x1);
    float r1 = x1 - __uint_as_float(h1 << 16);
    unsigned int l1 = bf16rn(r1);
    hp = h0 | (h1 << 16);
    lp = l0 | (l1 << 16);
}

// ---------------- routing ----------------------------------------------------
__global__ void zero_cnt_kernel() {
    if (threadIdx.x < ES) g_cnt[threadIdx.x] = 0;
}

__global__ void build_kernel(const int* __restrict__ idx,
                             const float* __restrict__ w) {
    int t = blockIdx.x * blockDim.x + threadIdx.x;
    if (t >= TS) return;
    int e0 = idx[2 * t];
    int e1 = idx[2 * t + 1];
    float w0 = w[2 * t];
    float w1 = w[2 * t + 1];
    if ((unsigned)e0 >= ES) e0 = 0;
    if ((unsigned)e1 >= ES) e1 = 0;
    if (e0 == e1) {
        int s = atomicAdd(&g_cnt[e0], 1);
        g_tok[e0 * CAP + s] = t;
        g_wt [e0 * CAP + s] = w0 + w1;
        g_slot0[t] = e0 * CAP + s;
        g_slot1[t] = -1;
    } else {
        int s0 = atomicAdd(&g_cnt[e0], 1);
        g_tok[e0 * CAP + s0] = t;
        g_wt [e0 * CAP + s0] = w0;
        int s1 = atomicAdd(&g_cnt[e1], 1);
        g_tok[e1 * CAP + s1] = t;
        g_wt [e1 * CAP + s1] = w1;
        g_slot0[t] = e0 * CAP + s0;
        g_slot1[t] = e1 * CAP + s1;
    }
}

// ---------------- fused gate+up GEMM (wmma bf16 3-term split) ----------------
// CTA tile: 128 gathered rows x 64 H-cols. K-tile = 16 fp32 (split in-kernel).
// Warps 4(m) x 2(n); warp tile 32x32 for each of g and u.
// smem rows padded to 48B (LDM=24) -> conflict-free ldmatrix phases.
__global__ void gateup_kernel(const float* __restrict__ X,
                              const float* __restrict__ Wg,
                              const float* __restrict__ Wu,
                              const int* __restrict__ dummy) {
    __shared__ unsigned int sAhi[2][128][LDW], sAlo[2][128][LDW];
    __shared__ unsigned int sBghi[2][64][LDW], sBglo[2][64][LDW];
    __shared__ unsigned int sBuhi[2][64][LDW], sBulo[2][64][LDW];
    // 2*128*48*2 + 4*2*64*48 = 49152 B = 48 KiB exactly.
    // Epilogue staging reuses sAhi (dead after mainloop): 8 warps * 1 KiB.

    int e = blockIdx.z;
    int cnt = g_cnt[e];
    int m0 = blockIdx.x * 128;
    if (m0 >= cnt) return;
    int n0 = blockIdx.y * 64;

    int tid = threadIdx.x;
    int wid = tid >> 5, lane = tid & 31;
    int wm = wid & 3, wn = wid >> 2;

    // loader mapping
    int rowA = tid >> 1;
    int kA = (tid & 1) * 8;            // 8 fp32 per thread for A
    int slotA = m0 + rowA;
    int token = (slotA < cnt) ? g_tok[e * CAP + slotA] : 0;
    const float* Arow = X + (size_t)token * DS;

    int rowB = (tid & 127) >> 1;
    int kB = (tid & 1) * 8;
    bool doU = (tid >= 128);
    const float* Brow = (doU ? Wu : Wg) + ((size_t)e * HS + n0 + rowB) * DS;

    wmma::fragment<wmma::accumulator, 16, 16, 16, float> accg[2][2], accu[2][2];
#pragma unroll
    for (int mi = 0; mi < 2; mi++)
#pragma unroll
        for (int ni = 0; ni < 2; ni++) {
            wmma::fill_fragment(accg[mi][ni], 0.0f);
            wmma::fill_fragment(accu[mi][ni], 0.0f);
        }

    // prime: load tile 0 into regs, split+store to buf 0
    float4 fa0 = *(const float4*)(Arow + kA);
    float4 fa1 = *(const float4*)(Arow + kA + 4);
    float4 fb0 = *(const float4*)(Brow + kB);
    float4 fb1 = *(const float4*)(Brow + kB + 4);
    {
        int ia = (tid & 1) * 4;
        unsigned int hp, lp;
        split2pack(fa0.x, fa0.y, hp, lp); sAhi[0][rowA][ia + 0] = hp; sAlo[0][rowA][ia + 0] = lp;
        split2pack(fa0.z, fa0.w, hp, lp); sAhi[0][rowA][ia + 1] = hp; sAlo[0][rowA][ia + 1] = lp;
        split2pack(fa1.x, fa1.y, hp, lp); sAhi[0][rowA][ia + 2] = hp; sAlo[0][rowA][ia + 2] = lp;
        split2pack(fa1.z, fa1.w, hp, lp); sAhi[0][rowA][ia + 3] = hp; sAlo[0][rowA][ia + 3] = lp;
        unsigned int (*bh)[LDW] = doU ? sBuhi[0] : sBghi[0];
        unsigned int (*bl)[LDW] = doU ? sBulo[0] : sBglo[0];
        split2pack(fb0.x, fb0.y, hp, lp); bh[rowB][ia + 0] = hp; bl[rowB][ia + 0] = lp;
        split2pack(fb0.z, fb0.w, hp, lp); bh[rowB][ia + 1] = hp; bl[rowB][ia + 1] = lp;
        split2pack(fb1.x, fb1.y, hp, lp); bh[rowB][ia + 2] = hp; bl[rowB][ia + 2] = lp;
        split2pack(fb1.z, fb1.w, hp, lp); bh[rowB][ia + 3] = hp; bl[rowB][ia + 3] = lp;
    }
    __syncthreads();

    const int NKT = DS / 16;  // 64
    for (int kt = 0; kt < NKT; kt++) {
        int buf = kt & 1;
        if (kt + 1 < NKT) {
            int kg = (kt + 1) * 16;
            fa0 = *(const float4*)(Arow + kg + kA);
            fa1 = *(const float4*)(Arow + kg + kA + 4);
            fb0 = *(const float4*)(Brow + kg + kB);
            fb1 = *(const float4*)(Brow + kg + kB + 4);
        }

        wmma::fragment<wmma::matrix_a, 16, 16, 16, __nv_bfloat16, wmma::row_major> fahi[2], falo[2];
#pragma unroll
        for (int mi = 0; mi < 2; mi++) {
            wmma::load_matrix_sync(fahi[mi], (const __nv_bfloat16*)&sAhi[buf][wm * 32 + mi * 16][0], LDM);
            wmma::load_matrix_sync(falo[mi], (const __nv_bfloat16*)&sAlo[buf][wm * 32 + mi * 16][0], LDM);
        }
#pragma unroll
        for (int ni = 0; ni < 2; ni++) {
            wmma::fragment<wmma::matrix_b, 16, 16, 16, __nv_bfloat16, wmma::col_major> fbgh, fbgl, fbuh, fbul;
            int nrow = wn * 32 + ni * 16;
            wmma::load_matrix_sync(fbgh, (const __nv_bfloat16*)&sBghi[buf][nrow][0], LDM);
            wmma::load_matrix_sync(fbgl, (const __nv_bfloat16*)&sBglo[buf][nrow][0], LDM);
            wmma::load_matrix_sync(fbuh, (const __nv_bfloat16*)&sBuhi[buf][nrow][0], LDM);
            wmma::load_matrix_sync(fbul, (const __nv_bfloat16*)&sBulo[buf][nrow][0], LDM);
#pragma unroll
            for (int mi = 0; mi < 2; mi++) {
                wmma::mma_sync(accg[mi][ni], fahi[mi], fbgh, accg[mi][ni]);
                wmma::mma_sync(accg[mi][ni], fahi[mi], fbgl, accg[mi][ni]);
                wmma::mma_sync(accg[mi][ni], falo[mi], fbgh, accg[mi][ni]);
                wmma::mma_sync(accu[mi][ni], fahi[mi], fbuh, accu[mi][ni]);
                wmma::mma_sync(accu[mi][ni], fahi[mi], fbul, accu[mi][ni]);
                wmma::mma_sync(accu[mi][ni], falo[mi], fbuh, accu[mi][ni]);
            }
        }

        if (kt + 1 < NKT) {
            int nb = buf ^ 1;
            int ia = (tid & 1) * 4;
            unsigned int hp, lp;
            split2pack(fa0.x, fa0.y, hp, lp); sAhi[nb][rowA][ia + 0] = hp; sAlo[nb][rowA][ia + 0] = lp;
            split2pack(fa0.z, fa0.w, hp, lp); sAhi[nb][rowA][ia + 1] = hp; sAlo[nb][rowA][ia + 1] = lp;
            split2pack(fa1.x, fa1.y, hp, lp); sAhi[nb][rowA][ia + 2] = hp; sAlo[nb][rowA][ia + 2] = lp;
            split2pack(fa1.z, fa1.w, hp, lp); sAhi[nb][rowA][ia + 3] = hp; sAlo[nb][rowA][ia + 3] = lp;
            unsigned int (*bh)[LDW] = doU ? sBuhi[nb] : sBghi[nb];
            unsigned int (*bl)[LDW] = doU ? sBulo[nb] : sBglo[nb];
            split2pack(fb0.x, fb0.y, hp, lp); bh[rowB][ia + 0] = hp; bl[rowB][ia + 0] = lp;
            split2pack(fb0.z, fb0.w, hp, lp); bh[rowB][ia + 1] = hp; bl[rowB][ia + 1] = lp;
            split2pack(fb1.x, fb1.y, hp, lp); bh[rowB][ia + 2] = hp; bl[rowB][ia + 2] = lp;
            split2pack(fb1.z, fb1.w, hp, lp); bh[rowB][ia + 3] = hp; bl[rowB][ia + 3] = lp;
            __syncthreads();
        }
    }

    // mainloop done; sAhi is dead -> reuse as per-warp f32 staging
    __syncthreads();
    float* stg = (float*)(&sAhi[0][0][0]) + wid * 256;

    // epilogue: silu(g)*u*w, split, element-wise u32 stores to hi/lo H images
    int ecap = e * CAP;
    int r = lane >> 1, c0 = (lane & 1) * 8;
#pragma unroll
    for (int mi = 0; mi < 2; mi++)
#pragma unroll
        for (int ni = 0; ni < 2; ni++) {
            wmma::store_matrix_sync(stg, accg[mi][ni], 16, wmma::mem_row_major);
            __syncwarp();
            float4 gv0 = *(const float4*)&stg[r * 16 + c0];
            float4 gv1 = *(const float4*)&stg[r * 16 + c0 + 4];
            __syncwarp();
            wmma::store_matrix_sync(stg, accu[mi][ni], 16, wmma::mem_row_major);
            __syncwarp();
            float4 uv0 = *(const float4*)&stg[r * 16 + c0];
            float4 uv1 = *(const float4*)&stg[r * 16 + c0 + 4];
            __syncwarp();
            int slot = m0 + wm * 32 + mi * 16 + r;
            if (slot < cnt) {
                float wv = g_wt[ecap + slot];
                float o0 = (gv0.x / (1.0f + __expf(-gv0.x))) * uv0.x * wv;
                float o1 = (gv0.y / (1.0f + __expf(-gv0.y))) * uv0.y * wv;
                float o2 = (gv0.z / (1.0f + __expf(-gv0.z))) * uv0.z * wv;
                float o3 = (gv0.w / (1.0f + __expf(-gv0.w))) * uv0.w * wv;
                float o4 = (gv1.x / (1.0f + __expf(-gv1.x))) * uv1.x * wv;
                float o5 = (gv1.y / (1.0f + __expf(-gv1.y))) * uv1.y * wv;
                float o6 = (gv1.z / (1.0f + __expf(-gv1.z))) * uv1.z * wv;
                float o7 = (gv1.w / (1.0f + __expf(-gv1.w))) * uv1.w * wv;
                unsigned int hp0, lp0, hp1, lp1, hp2, lp2, hp3, lp3;
                split2pack(o0, o1, hp0, lp0);
                split2pack(o2, o3, hp1, lp1);
                split2pack(o4, o5, hp2, lp2);
                split2pack(o6, o7, hp3, lp3);
                size_t hoff = (size_t)(ecap + slot) * HS + n0 + wn * 32 + ni * 16 + c0;
                unsigned int* dh = (unsigned int*)(g_Hhi + hoff);
                unsigned int* dl = (unsigned int*)(g_Hlo + hoff);
                dh[0] = hp0; dh[1] = hp1; dh[2] = hp2; dh[3] = hp3;
                dl[0] = lp0; dl[1] = lp1; dl[2] = lp2; dl[3] = lp3;
            }
        }
}

// ---------------- down GEMM: O = H @ Wd^T (A pre-split, B split in-loop) -----
// CTA tile: 128 rows x 128 DOUT-cols. K-tile 16 over HS=2048.
// Warps 4(m) x 2(n); warp tile 32 x 64. smem rows padded to 48B.
__global__ void down_kernel(const float* __restrict__ Wd) {
    __shared__ unsigned int sAhi[2][128][LDW], sAlo[2][128][LDW];
    __shared__ unsigned int sBhi[2][128][LDW], sBlo[2][128][LDW];
    // 4 * 2*128*48 = 49152 B = 48 KiB exactly

    int e = blockIdx.z;
    int cnt = g_cnt[e];
    int m0 = blockIdx.x * 128;
    if (m0 >= cnt) return;
    int n0 = blockIdx.y * 128;
    int ecap = e * CAP;

    int tid = threadIdx.x;
    int wid = tid >> 5;
    int wm = wid & 3, wn = wid >> 2;

    // A loader: pre-split images; row = tid>>1, seg = (tid&1)*8 (u16 elems)
    int rowA = tid >> 1, segA = (tid & 1) * 8;
    const unsigned short* Ahirow = g_Hhi + (size_t)(ecap + m0 + rowA) * HS + segA;
    const unsigned short* Alorow = g_Hlo + (size_t)(ecap + m0 + rowA) * HS + segA;

    // B loader: fp32 Wd, split in-loop; row = tid>>1, seg = (tid&1)*8 fp32
    int rowB = tid >> 1, kB = (tid & 1) * 8;
    const float* Brow = Wd + ((size_t)e * DOUTS + n0 + rowB) * HS + kB;

    wmma::fragment<wmma::accumulator, 16, 16, 16, float> acc[2][4];
#pragma unroll
    for (int mi = 0; mi < 2; mi++)
#pragma unroll
        for (int ni = 0; ni < 4; ni++)
            wmma::fill_fragment(acc[mi][ni], 0.0f);

    // prime
    uint4 pAh = *(const uint4*)(Ahirow);
    uint4 pAl = *(const uint4*)(Alorow);
    float4 fb0 = *(const float4*)(Brow);
    float4 fb1 = *(const float4*)(Brow + 4);
    {
        int ia = (tid & 1) * 4;
        sAhi[0][rowA][ia + 0] = pAh.x; sAhi[0][rowA][ia + 1] = pAh.y;
        sAhi[0][rowA][ia + 2] = pAh.z; sAhi[0][rowA][ia + 3] = pAh.w;
        sAlo[0][rowA][ia + 0] = pAl.x; sAlo[0][rowA][ia + 1] = pAl.y;
        sAlo[0][rowA][ia + 2] = pAl.z; sAlo[0][rowA][ia + 3] = pAl.w;
        unsigned int hp, lp;
        split2pack(fb0.x, fb0.y, hp, lp); sBhi[0][rowB][ia + 0] = hp; sBlo[0][rowB][ia + 0] = lp;
        split2pack(fb0.z, fb0.w, hp, lp); sBhi[0][rowB][ia + 1] = hp; sBlo[0][rowB][ia + 1] = lp;
        split2pack(fb1.x, fb1.y, hp, lp); sBhi[0][rowB][ia + 2] = hp; sBlo[0][rowB][ia + 2] = lp;
        split2pack(fb1.z, fb1.w, hp, lp); sBhi[0][rowB][ia + 3] = hp; sBlo[0][rowB][ia + 3] = lp;
    }
    __syncthreads();

    const int NKT = HS / 16;  // 128
    for (int kt = 0; kt < NKT; kt++) {
        int buf = kt & 1;
        if (kt + 1 < NKT) {
            int kg = (kt + 1) * 16;
            pAh = *(const uint4*)(Ahirow + kg);
            pAl = *(const uint4*)(Alorow + kg);
            fb0 = *(const float4*)(Brow + kg);
            fb1 = *(const float4*)(Brow + kg + 4);
        }

        wmma::fragment<wmma::matrix_a, 16, 16, 16, __nv_bfloat16, wmma::row_major> fahi[2], falo[2];
#pragma unroll
        for (int mi = 0; mi < 2; mi++) {
            wmma::load_matrix_sync(fahi[mi], (const __nv_bfloat16*)&sAhi[buf][wm * 32 + mi * 16][0], LDM);
            wmma::load_matrix_sync(falo[mi], (const __nv_bfloat16*)&sAlo[buf][wm * 32 + mi * 16][0], LDM);
        }
#pragma unroll
        for (int ni = 0; ni < 4; ni++) {
            wmma::fragment<wmma::matrix_b, 16, 16, 16, __nv_bfloat16, wmma::col_major> fbh, fbl;
            int nrow = wn * 64 + ni * 16;
            wmma::load_matrix_sync(fbh, (const __nv_bfloat16*)&sBhi[buf][nrow][0], LDM);
            wmma::load_matrix_sync(fbl, (const __nv_bfloat16*)&sBlo[buf][nrow][0], LDM);
#pragma unroll
            for (int mi = 0; mi < 2; mi++) {
                wmma::mma_sync(acc[mi][ni], fahi[mi], fbh, acc[mi][ni]);
                wmma::mma_sync(acc[mi][ni], fahi[mi], fbl, acc[mi][ni]);
                wmma::mma_sync(acc[mi][ni], falo[mi], fbh, acc[mi][ni]);
            }
        }

        if (kt + 1 < NKT) {
            int nb = buf ^ 1;
            int ia = (tid & 1) * 4;
            sAhi[nb][rowA][ia + 0] = pAh.x; sAhi[nb][rowA][ia + 1] = pAh.y;
            sAhi[nb][rowA][ia + 2] = pAh.z; sAhi[nb][rowA][ia + 3] = pAh.w;
            sAlo[nb][rowA][ia + 0] = pAl.x; sAlo[nb][rowA][ia + 1] = pAl.y;
            sAlo[nb][rowA][ia + 2] = pAl.z; sAlo[nb][rowA][ia + 3] = pAl.w;
            unsigned int hp, lp;
            split2pack(fb0.x, fb0.y, hp, lp); sBhi[nb][rowB][ia + 0] = hp; sBlo[nb][rowB][ia + 0] = lp;
            split2pack(fb0.z, fb0.w, hp, lp); sBhi[nb][rowB][ia + 1] = hp; sBlo[nb][rowB][ia + 1] = lp;
            split2pack(fb1.x, fb1.y, hp, lp); sBhi[nb][rowB][ia + 2] = hp; sBlo[nb][rowB][ia + 2] = lp;
            split2pack(fb1.z, fb1.w, hp, lp); sBhi[nb][rowB][ia + 3] = hp; sBlo[nb][rowB][ia + 3] = lp;
            __syncthreads();
        }
    }

    // epilogue: direct wmma store to global (unused rows harmless, never read)
#pragma unroll
    for (int mi = 0; mi < 2; mi++)
#pragma unroll
        for (int ni = 0; ni < 4; ni++) {
            float* dst = g_O + (size_t)(ecap + m0 + wm * 32 + mi * 16) * DOUTS
                       + n0 + wn * 64 + ni * 16;
            wmma::store_matrix_sync(dst, acc[mi][ni], DOUTS, wmma::mem_row_major);
        }
}

// ---------------- final combine ---------------------------------------------
__global__ void combine_kernel(float* __restrict__ out) {
    int i = blockIdx.x * blockDim.x + threadIdx.x;  // over TS*DOUTS/4
    if (i >= TS * (DOUTS / 4)) return;
    int t  = i / (DOUTS / 4);
    int d4 = i % (DOUTS / 4);
    const float4* O4 = (const float4*)g_O;
    float4 a = O4[(size_t)g_slot0[t] * (DOUTS / 4) + d4];
    int s1 = g_slot1[t];
    if (s1 >= 0) {
        float4 b = O4[(size_t)s1 * (DOUTS / 4) + d4];
        a.x += b.x; a.y += b.y; a.z += b.z; a.w += b.w;
    }
    ((float4*)out)[i] = a;
}

// ---------------- launch -----------------------------------------------------
extern "C" void kernel_launch(void* const* d_in, const int* in_sizes, int n_in,
                              void* d_out, int out_size) {
    const float* X   = (const float*)d_in[0];   // [T, D]
    const int*   idx = (const int*)d_in[1];     // [T, K] int32 (JAX default)
    const float* wts = (const float*)d_in[2];   // [T, K]
    const float* Wg  = (const float*)d_in[3];   // [E, H, D]
    const float* Wu  = (const float*)d_in[4];   // [E, H, D]
    const float* Wd  = (const float*)d_in[5];   // [E, DOUT, H]
    float* out = (float*)d_out;                 // [T, DOUT]

    zero_cnt_kernel<<<1, 32>>>();
    build_kernel<<<(TS + 255) / 256, 256>>>(idx, wts);

    dim3 gUp(CAP / 128, HS / 64, ES);           // 64 x 32 x 8 (early-exit on count)
    gateup_kernel<<<gUp, 256>>>(X, Wg, Wu, idx);

    dim3 gDn(CAP / 128, DOUTS / 128, ES);       // 64 x 8 x 8
    down_kernel<<<gDn, 256>>>(Wd);

    combine_kernel<<<(TS * (DOUTS / 4) + 255) / 256, 256>>>(out);
}